// round 12
// baseline (speedup 1.0000x reference)
#include <cuda_runtime.h>
#include <cstdint>

#define BATCH 512
#define SEQ   512
#define EMB   128
#define HID   64
#define GATES 256   // 4*HID
#define VOCAB 50000

// 51.2 MB token->xproj table: table[v][g] = dot(emb[v], Wih0[g]) + bih0[g] + bhh0[g]
__device__ float g_tab[(size_t)VOCAB * GATES];

// ---------------- packed f32x2 helpers ----------------
static __device__ __forceinline__ unsigned long long pk2(float lo, float hi) {
    unsigned long long v;
    asm("mov.b64 %0, {%1, %2};" : "=l"(v) : "f"(lo), "f"(hi));
    return v;
}
static __device__ __forceinline__ void upk2(unsigned long long v, float& lo, float& hi) {
    asm("mov.b64 {%0, %1}, %2;" : "=f"(lo), "=f"(hi) : "l"(v));
}
static __device__ __forceinline__ void fma2(unsigned long long& a,
                                            unsigned long long x,
                                            unsigned long long w) {
    asm("fma.rn.f32x2 %0, %1, %2, %0;" : "+l"(a) : "l"(x), "l"(w));
}
static __device__ __forceinline__ float tanh_f(float x) {
    float y;
    asm("tanh.approx.f32 %0, %1;" : "=f"(y) : "f"(x));
    return y;
}
static __device__ __forceinline__ float sig_f(float x) {
    return fmaf(0.5f, tanh_f(0.5f * x), 0.5f);
}

// ======================================================================
// Kernel 1: token table build. table[v][g] = emb[v] . Wih0[g] + b0[g].
// ======================================================================
#define XT_STRIDE 136

__global__ void __launch_bounds__(256, 2)
k_table(const float* __restrict__ emb,
        const float* __restrict__ Wih0,
        const float* __restrict__ bih0,
        const float* __restrict__ bhh0,
        float* __restrict__ tab)
{
    __shared__ float xs[16 * XT_STRIDE];

    const int tid  = threadIdx.x;
    const int gl   = tid >> 1;
    const int half = tid & 1;
    const int g    = blockIdx.y * 128 + gl;

    unsigned long long w[32];
#pragma unroll
    for (int j = 0; j < 16; ++j) {
        ulonglong2 v = *(const ulonglong2*)&Wih0[g * EMB + half * 64 + j * 4];
        w[2 * j] = v.x;  w[2 * j + 1] = v.y;
    }
    const float b0 = (half == 0) ? (__ldg(&bih0[g]) + __ldg(&bhh0[g])) : 0.f;

    const int v0 = blockIdx.x * 128;

#pragma unroll 1
    for (int tile = 0; tile < 8; ++tile) {
        const int vbase = v0 + tile * 16;
        if (vbase >= VOCAB) break;
        const int rows = min(16, VOCAB - vbase);

        __syncthreads();
        for (int j = tid; j < rows * 32; j += 256) {
            const int r = j >> 5, k4 = j & 31;
            const int dst = r * XT_STRIDE + (k4 < 16 ? k4 * 4 : 68 + (k4 - 16) * 4);
            *(float4*)&xs[dst] = *(const float4*)&emb[(size_t)(vbase + r) * EMB + k4 * 4];
        }
        __syncthreads();

        unsigned long long acc[16];
#pragma unroll
        for (int r = 0; r < 16; ++r) acc[r] = pk2(b0, 0.f);

#pragma unroll
        for (int kc = 0; kc < 16; ++kc) {
#pragma unroll
            for (int r = 0; r < 16; ++r) {
                const ulonglong2 x = *(const ulonglong2*)&xs[r * XT_STRIDE + half * 68 + kc * 4];
                fma2(acc[r], x.x, w[2 * kc]);
                fma2(acc[r], x.y, w[2 * kc + 1]);
            }
        }
#pragma unroll
        for (int r = 0; r < 16; ++r) {
            float lo, hi; upk2(acc[r], lo, hi);
            float s = lo + hi;
            s += __shfl_xor_sync(0xFFFFFFFFu, s, 1);
            if (half == 0 && r < rows)
                tab[(size_t)(vbase + r) * GATES + g] = s;
        }
    }
}

// ======================================================================
// Kernel 2: fused 2-layer LSTM scan + FC, layer-pipelined (layer1 lags
// layer0 by one step), 2 barriers per step. 128 blocks x 256 threads;
// block owns batch rows 4b..4b+3. Thread = gate.
//   - Whh0 rows in registers (64 regs)
//   - Wih1 / Whh1 rows in SMEM, XOR-swizzled (group js=(j+g)&15) ->
//     conflict-free lane-distinct LDS.128, no padding (64 KB each)
//   - xproj from token table, one-step register prefetch
// Per step: [gates1(t-1); gates0(t)] bar [elem0(t)+elem1(t-1)] bar.
// ======================================================================
__global__ void __launch_bounds__(256, 1)
k_scan(const int* __restrict__ seq32,
       const float* __restrict__ tab,
       const float* __restrict__ Whh0, const float* __restrict__ Wih1,
       const float* __restrict__ Whh1,
       const float* __restrict__ bih1, const float* __restrict__ bhh1,
       const float* __restrict__ Wfc,  const float* __restrict__ bfc,
       float* __restrict__ out)
{
    extern __shared__ float sm[];
    float* wi1s = sm;                      // 256*64 swizzled
    float* wh1s = wi1s + 256 * HID;        // 256*64 swizzled
    float* h0s  = wh1s + 256 * HID;        // 4*64
    float* h1s  = h0s + 256;               // 4*64
    float* gA   = h1s + 256;               // 4*256 (layer0 gates)
    float* gB   = gA + 1024;               // 4*256 (layer1 gates)
    int4*  tok4 = (int4*)(gB + 1024);      // SEQ int4

    const int tid  = threadIdx.x;
    const int g    = tid;                  // gate index
    const int row0 = blockIdx.x * 4;

    // ---- Whh0 row in registers (32 f32x2 = 64 regs)
    unsigned long long w0[32];
#pragma unroll
    for (int j = 0; j < 16; ++j) {
        ulonglong2 v = *(const ulonglong2*)&Whh0[g * HID + j * 4];
        w0[2 * j] = v.x;  w0[2 * j + 1] = v.y;
    }
    // ---- Wih1 / Whh1 into swizzled smem: group grp of gate gg stored at
    //      position (grp+gg)&15 within the row.
    for (int j = tid; j < 256 * 16; j += 256) {
        const int gg = j >> 4, grp = j & 15;
        const int dst = gg * HID + (((grp + gg) & 15) << 2);
        *(float4*)&wi1s[dst] = *(const float4*)&Wih1[gg * HID + (grp << 2)];
        *(float4*)&wh1s[dst] = *(const float4*)&Whh1[gg * HID + (grp << 2)];
    }

    const float b1 = __ldg(&bih1[g]) + __ldg(&bhh1[g]);

    // int64 vs int32 input_seq detection
    const bool is64 = ((__ldg(seq32 + 1) | __ldg(seq32 + 3) | __ldg(seq32 + 5) |
                        __ldg(seq32 + 7) | __ldg(seq32 + 9) | __ldg(seq32 + 11) |
                        __ldg(seq32 + 13) | __ldg(seq32 + 15)) == 0);

    // ---- stage tokens (tok4[t] = tokens of the 4 rows at step t)
    for (int t = tid; t < SEQ; t += 256) {
        int4 v;
        if (is64) {
            v.x = __ldg(seq32 + 2 * ((row0 + 0) * SEQ + t));
            v.y = __ldg(seq32 + 2 * ((row0 + 1) * SEQ + t));
            v.z = __ldg(seq32 + 2 * ((row0 + 2) * SEQ + t));
            v.w = __ldg(seq32 + 2 * ((row0 + 3) * SEQ + t));
        } else {
            v.x = __ldg(seq32 + (row0 + 0) * SEQ + t);
            v.y = __ldg(seq32 + (row0 + 1) * SEQ + t);
            v.z = __ldg(seq32 + (row0 + 2) * SEQ + t);
            v.w = __ldg(seq32 + (row0 + 3) * SEQ + t);
        }
        tok4[t] = v;
    }
    for (int j = tid; j < 256; j += 256) {   // 4*HID == 256 == blockDim
        h0s[j] = 0.f;
        h1s[j] = 0.f;
    }

    const int rr = tid >> 6;       // elem row
    const int u  = tid & 63;       // elem unit
    float c0 = 0.f, c1 = 0.f;

    __syncthreads();   // weights / tok4 / h ready

    // ---- xproj(0) and prefetch xproj(1)
    float x0, x1, x2, x3, p0, p1, p2, p3;
    {
        int4 tk = tok4[0];
        x0 = __ldg(&tab[(size_t)tk.x * GATES + g]);
        x1 = __ldg(&tab[(size_t)tk.y * GATES + g]);
        x2 = __ldg(&tab[(size_t)tk.z * GATES + g]);
        x3 = __ldg(&tab[(size_t)tk.w * GATES + g]);
        tk = tok4[1];
        p0 = __ldg(&tab[(size_t)tk.x * GATES + g]);
        p1 = __ldg(&tab[(size_t)tk.y * GATES + g]);
        p2 = __ldg(&tab[(size_t)tk.z * GATES + g]);
        p3 = __ldg(&tab[(size_t)tk.w * GATES + g]);
    }

    // ---- prologue t=0: gates0(0) = xproj(0) (h0(-1)=0) -> elem0
    gA[0 * GATES + g] = x0;
    gA[1 * GATES + g] = x1;
    gA[2 * GATES + g] = x2;
    gA[3 * GATES + g] = x3;
    __syncthreads();
    {
        const float* gr = gA + rr * GATES;
        float i_ = sig_f(gr[u]);
        float g_ = tanh_f(gr[128 + u]);
        float o_ = sig_f(gr[192 + u]);
        c0 = i_ * g_;
        h0s[rr * HID + u] = o_ * tanh_f(c0);
    }
    __syncthreads();
    x0 = p0; x1 = p1; x2 = p2; x3 = p3;

    const int gbase = g * HID;

    // ======== steady state: t = 1 .. SEQ-1 ========
#pragma unroll 1
    for (int t = 1; t < SEQ; ++t) {
        // prefetch xproj(t+1): covered by the full GEMM phase
        if (t + 1 < SEQ) {
            const int4 tk = tok4[t + 1];
            p0 = __ldg(&tab[(size_t)tk.x * GATES + g]);
            p1 = __ldg(&tab[(size_t)tk.y * GATES + g]);
            p2 = __ldg(&tab[(size_t)tk.z * GATES + g]);
            p3 = __ldg(&tab[(size_t)tk.w * GATES + g]);
        }

        // ---- fused GEMM phase -------------------------------------
        // gates1(t-1) = b1 + h0(t-1)·Wih1 + h1(t-2)·Whh1  (smem weights)
        {
            unsigned long long a[4];
#pragma unroll
            for (int r = 0; r < 4; ++r) a[r] = pk2(b1, 0.f);
#pragma unroll
            for (int kc = 0; kc < 16; ++kc) {
                const int sw = gbase + (((kc + g) & 15) << 2);   // swizzled grp kc
                const ulonglong2 wiv = *(const ulonglong2*)&wi1s[sw];
                const ulonglong2 whv = *(const ulonglong2*)&wh1s[sw];
#pragma unroll
                for (int r = 0; r < 4; ++r) {
                    const ulonglong2 h0v = *(const ulonglong2*)&h0s[r * HID + kc * 4];
                    fma2(a[r], h0v.x, wiv.x);
                    fma2(a[r], h0v.y, wiv.y);
                    const ulonglong2 h1v = *(const ulonglong2*)&h1s[r * HID + kc * 4];
                    fma2(a[r], h1v.x, whv.x);
                    fma2(a[r], h1v.y, whv.y);
                }
            }
#pragma unroll
            for (int r = 0; r < 4; ++r) {
                float lo, hi; upk2(a[r], lo, hi);
                gB[r * GATES + g] = lo + hi;
            }
        }
        // gates0(t) = xproj(t) + h0(t-1)·Whh0  (register weights)
        {
            unsigned long long a[4];
            a[0] = pk2(x0, 0.f); a[1] = pk2(x1, 0.f);
            a[2] = pk2(x2, 0.f); a[3] = pk2(x3, 0.f);
#pragma unroll
            for (int kc = 0; kc < 16; ++kc) {
#pragma unroll
                for (int r = 0; r < 4; ++r) {
                    const ulonglong2 h = *(const ulonglong2*)&h0s[r * HID + kc * 4];
                    fma2(a[r], h.x, w0[2 * kc]);
                    fma2(a[r], h.y, w0[2 * kc + 1]);
                }
            }
#pragma unroll
            for (int r = 0; r < 4; ++r) {
                float lo, hi; upk2(a[r], lo, hi);
                gA[r * GATES + g] = lo + hi;
            }
        }
        __syncthreads();   // (1) gA/gB ready; all h reads complete

        // ---- fused elementwise: layer0(t) and layer1(t-1) for (rr,u)
        {
            const float* gr = gA + rr * GATES;
            float i_ = sig_f(gr[u]);
            float f_ = sig_f(gr[64 + u]);
            float g_ = tanh_f(gr[128 + u]);
            float o_ = sig_f(gr[192 + u]);
            c0 = f_ * c0 + i_ * g_;
            h0s[rr * HID + u] = o_ * tanh_f(c0);
        }
        {
            const float* gr = gB + rr * GATES;
            float i_ = sig_f(gr[u]);
            float f_ = sig_f(gr[64 + u]);
            float g_ = tanh_f(gr[128 + u]);
            float o_ = sig_f(gr[192 + u]);
            c1 = f_ * c1 + i_ * g_;
            h1s[rr * HID + u] = o_ * tanh_f(c1);
        }
        __syncthreads();   // (2) h0(t), h1(t-1) published

        x0 = p0; x1 = p1; x2 = p2; x3 = p3;
    }

    // ======== epilogue: gates1(SEQ-1) -> h1(SEQ-1) ========
    {
        unsigned long long a[4];
#pragma unroll
        for (int r = 0; r < 4; ++r) a[r] = pk2(b1, 0.f);
#pragma unroll
        for (int kc = 0; kc < 16; ++kc) {
            const int sw = gbase + (((kc + g) & 15) << 2);
            const ulonglong2 wiv = *(const ulonglong2*)&wi1s[sw];
            const ulonglong2 whv = *(const ulonglong2*)&wh1s[sw];
#pragma unroll
            for (int r = 0; r < 4; ++r) {
                const ulonglong2 h0v = *(const ulonglong2*)&h0s[r * HID + kc * 4];
                fma2(a[r], h0v.x, wiv.x);
                fma2(a[r], h0v.y, wiv.y);
                const ulonglong2 h1v = *(const ulonglong2*)&h1s[r * HID + kc * 4];
                fma2(a[r], h1v.x, whv.x);
                fma2(a[r], h1v.y, whv.y);
            }
        }
#pragma unroll
        for (int r = 0; r < 4; ++r) {
            float lo, hi; upk2(a[r], lo, hi);
            gB[r * GATES + g] = lo + hi;
        }
    }
    __syncthreads();
    {
        const float* gr = gB + rr * GATES;
        float i_ = sig_f(gr[u]);
        float f_ = sig_f(gr[64 + u]);
        float g_ = tanh_f(gr[128 + u]);
        float o_ = sig_f(gr[192 + u]);
        c1 = f_ * c1 + i_ * g_;
        h1s[rr * HID + u] = o_ * tanh_f(c1);
    }
    __syncthreads();

    // ---- Final FC + sigmoid on h1(SEQ-1)
    if (tid < 8) {
        int r = tid >> 1, o = tid & 1;
        float a = __ldg(&bfc[o]);
        for (int k = 0; k < HID; ++k)
            a = fmaf(h1s[r * HID + k], __ldg(&Wfc[o * HID + k]), a);
        out[(row0 + r) * 2 + o] = sig_f(a);
    }
}

// ======================================================================
extern "C" void kernel_launch(void* const* d_in, const int* in_sizes, int n_in,
                              void* d_out, int out_size) {
    const int*   seq32 = (const int*)d_in[0];
    const float* emb   = (const float*)d_in[1];
    const float* Wih0  = (const float*)d_in[2];
    const float* Whh0  = (const float*)d_in[3];
    const float* bih0  = (const float*)d_in[4];
    const float* bhh0  = (const float*)d_in[5];
    const float* Wih1  = (const float*)d_in[6];
    const float* Whh1  = (const float*)d_in[7];
    const float* bih1  = (const float*)d_in[8];
    const float* bhh1  = (const float*)d_in[9];
    const float* Wfc   = (const float*)d_in[10];
    const float* bfc   = (const float*)d_in[11];
    float* out = (float*)d_out;

    float* tab = nullptr;
    cudaGetSymbolAddress((void**)&tab, g_tab);

    // smem: wi1(16384) + wh1(16384) + h0(256) + h1(256) + gA(1024) +
    //       gB(1024) + tok4(512*4 ints)
    const int smem2 = (16384 + 16384 + 256 + 256 + 1024 + 1024 + SEQ * 4) * 4;
    cudaFuncSetAttribute(k_scan, cudaFuncAttributeMaxDynamicSharedMemorySize, smem2);

    dim3 gtab((VOCAB + 127) / 128, 2);
    k_table<<<gtab, 256>>>(emb, Wih0, bih0, bhh0, tab);
    k_scan<<<BATCH / 4, 256, smem2>>>(seq32, tab, Whh0, Wih1, Whh1,
                                      bih1, bhh1, Wfc, bfc, out);
}

// round 13
// speedup vs baseline: 3.3894x; 3.3894x over previous
#include <cuda_runtime.h>
#include <cstdint>

#define BATCH 512
#define SEQ   512
#define EMB   128
#define HID   64
#define GATES 256   // 4*HID
#define VOCAB 50000

// 51.2 MB token->xproj table: table[v][g] = dot(emb[v], Wih0[g]) + bih0[g] + bhh0[g]
__device__ float g_tab[(size_t)VOCAB * GATES];

// ---------------- packed f32x2 helpers ----------------
static __device__ __forceinline__ unsigned long long pk2(float lo, float hi) {
    unsigned long long v;
    asm("mov.b64 %0, {%1, %2};" : "=l"(v) : "f"(lo), "f"(hi));
    return v;
}
static __device__ __forceinline__ void upk2(unsigned long long v, float& lo, float& hi) {
    asm("mov.b64 {%0, %1}, %2;" : "=f"(lo), "=f"(hi) : "l"(v));
}
static __device__ __forceinline__ void fma2(unsigned long long& a,
                                            unsigned long long x,
                                            unsigned long long w) {
    asm("fma.rn.f32x2 %0, %1, %2, %0;" : "+l"(a) : "l"(x), "l"(w));
}
static __device__ __forceinline__ float tanh_f(float x) {
    float y;
    asm("tanh.approx.f32 %0, %1;" : "=f"(y) : "f"(x));
    return y;
}
static __device__ __forceinline__ float sig_f(float x) {
    return fmaf(0.5f, tanh_f(0.5f * x), 0.5f);
}

// ======================================================================
// Kernel 1: token table build. table[v][g] = emb[v] . Wih0[g] + b0[g].
// ======================================================================
#define XT_STRIDE 136

__global__ void __launch_bounds__(256, 2)
k_table(const float* __restrict__ emb,
        const float* __restrict__ Wih0,
        const float* __restrict__ bih0,
        const float* __restrict__ bhh0,
        float* __restrict__ tab)
{
    __shared__ float xs[16 * XT_STRIDE];

    const int tid  = threadIdx.x;
    const int gl   = tid >> 1;
    const int half = tid & 1;
    const int g    = blockIdx.y * 128 + gl;

    unsigned long long w[32];
#pragma unroll
    for (int j = 0; j < 16; ++j) {
        ulonglong2 v = *(const ulonglong2*)&Wih0[g * EMB + half * 64 + j * 4];
        w[2 * j] = v.x;  w[2 * j + 1] = v.y;
    }
    const float b0 = (half == 0) ? (__ldg(&bih0[g]) + __ldg(&bhh0[g])) : 0.f;

    const int v0 = blockIdx.x * 128;

#pragma unroll 1
    for (int tile = 0; tile < 8; ++tile) {
        const int vbase = v0 + tile * 16;
        if (vbase >= VOCAB) break;
        const int rows = min(16, VOCAB - vbase);

        __syncthreads();
        for (int j = tid; j < rows * 32; j += 256) {
            const int r = j >> 5, k4 = j & 31;
            const int dst = r * XT_STRIDE + (k4 < 16 ? k4 * 4 : 68 + (k4 - 16) * 4);
            *(float4*)&xs[dst] = *(const float4*)&emb[(size_t)(vbase + r) * EMB + k4 * 4];
        }
        __syncthreads();

        unsigned long long acc[16];
#pragma unroll
        for (int r = 0; r < 16; ++r) acc[r] = pk2(b0, 0.f);

#pragma unroll
        for (int kc = 0; kc < 16; ++kc) {
#pragma unroll
            for (int r = 0; r < 16; ++r) {
                const ulonglong2 x = *(const ulonglong2*)&xs[r * XT_STRIDE + half * 68 + kc * 4];
                fma2(acc[r], x.x, w[2 * kc]);
                fma2(acc[r], x.y, w[2 * kc + 1]);
            }
        }
#pragma unroll
        for (int r = 0; r < 16; ++r) {
            float lo, hi; upk2(acc[r], lo, hi);
            float s = lo + hi;
            s += __shfl_xor_sync(0xFFFFFFFFu, s, 1);
            if (half == 0 && r < rows)
                tab[(size_t)(vbase + r) * GATES + g] = s;
        }
    }
}

// ======================================================================
// Kernel 2: fused 2-layer LSTM scan + FC, layer-pipelined (layer1 lags
// layer0 by one step), 2 barriers per step. 128 blocks x 256 threads;
// block owns batch rows 4b..4b+3. Thread = gate.
//   - ALL weights (Whh0 / Wih1 / Whh1) in XOR-swizzled SMEM: zero
//     register weight arrays => nothing for ptxas to spill.
//   - kc loops use bounded unroll (2) to cap the LDS hoist window.
//   - xproj from token table, one-step register prefetch.
// Per step: [gates1(t-1); gates0(t)] bar [elem0(t)+elem1(t-1)] bar.
// ======================================================================
__global__ void __launch_bounds__(256, 1)
k_scan(const int* __restrict__ seq32,
       const float* __restrict__ tab,
       const float* __restrict__ Whh0, const float* __restrict__ Wih1,
       const float* __restrict__ Whh1,
       const float* __restrict__ bih1, const float* __restrict__ bhh1,
       const float* __restrict__ Wfc,  const float* __restrict__ bfc,
       float* __restrict__ out)
{
    extern __shared__ float sm[];
    float* w0s  = sm;                      // 256*64 swizzled Whh0
    float* wi1s = w0s + 256 * HID;         // 256*64 swizzled Wih1
    float* wh1s = wi1s + 256 * HID;        // 256*64 swizzled Whh1
    float* h0s  = wh1s + 256 * HID;        // 4*64
    float* h1s  = h0s + 256;               // 4*64
    float* gA   = h1s + 256;               // 4*256 (layer0 gates)
    float* gB   = gA + 1024;               // 4*256 (layer1 gates)
    int4*  tok4 = (int4*)(gB + 1024);      // SEQ int4

    const int tid  = threadIdx.x;
    const int g    = tid;                  // gate index
    const int row0 = blockIdx.x * 4;

    // ---- all weights into swizzled smem: group grp of gate gg stored at
    //      position (grp+gg)&15 within the row -> 8 consecutive gates hit
    //      8 distinct bank-quads (conflict-free LDS.128 phases).
    for (int j = tid; j < 256 * 16; j += 256) {
        const int gg = j >> 4, grp = j & 15;
        const int dst = gg * HID + (((grp + gg) & 15) << 2);
        *(float4*)&w0s[dst]  = *(const float4*)&Whh0[gg * HID + (grp << 2)];
        *(float4*)&wi1s[dst] = *(const float4*)&Wih1[gg * HID + (grp << 2)];
        *(float4*)&wh1s[dst] = *(const float4*)&Whh1[gg * HID + (grp << 2)];
    }

    const float b1 = __ldg(&bih1[g]) + __ldg(&bhh1[g]);

    // int64 vs int32 input_seq detection
    const bool is64 = ((__ldg(seq32 + 1) | __ldg(seq32 + 3) | __ldg(seq32 + 5) |
                        __ldg(seq32 + 7) | __ldg(seq32 + 9) | __ldg(seq32 + 11) |
                        __ldg(seq32 + 13) | __ldg(seq32 + 15)) == 0);

    // ---- stage tokens (tok4[t] = tokens of the 4 rows at step t)
    for (int t = tid; t < SEQ; t += 256) {
        int4 v;
        if (is64) {
            v.x = __ldg(seq32 + 2 * ((row0 + 0) * SEQ + t));
            v.y = __ldg(seq32 + 2 * ((row0 + 1) * SEQ + t));
            v.z = __ldg(seq32 + 2 * ((row0 + 2) * SEQ + t));
            v.w = __ldg(seq32 + 2 * ((row0 + 3) * SEQ + t));
        } else {
            v.x = __ldg(seq32 + (row0 + 0) * SEQ + t);
            v.y = __ldg(seq32 + (row0 + 1) * SEQ + t);
            v.z = __ldg(seq32 + (row0 + 2) * SEQ + t);
            v.w = __ldg(seq32 + (row0 + 3) * SEQ + t);
        }
        tok4[t] = v;
    }
    for (int j = tid; j < 256; j += 256) {   // 4*HID == 256 == blockDim
        h0s[j] = 0.f;
        h1s[j] = 0.f;
    }

    const int rr = tid >> 6;       // elem row
    const int u  = tid & 63;       // elem unit
    float c0 = 0.f, c1 = 0.f;

    __syncthreads();   // weights / tok4 / h ready

    // ---- xproj(0) and prefetch xproj(1)
    float x0, x1, x2, x3, p0, p1, p2, p3;
    {
        int4 tk = tok4[0];
        x0 = __ldg(&tab[(size_t)tk.x * GATES + g]);
        x1 = __ldg(&tab[(size_t)tk.y * GATES + g]);
        x2 = __ldg(&tab[(size_t)tk.z * GATES + g]);
        x3 = __ldg(&tab[(size_t)tk.w * GATES + g]);
        tk = tok4[1];
        p0 = __ldg(&tab[(size_t)tk.x * GATES + g]);
        p1 = __ldg(&tab[(size_t)tk.y * GATES + g]);
        p2 = __ldg(&tab[(size_t)tk.z * GATES + g]);
        p3 = __ldg(&tab[(size_t)tk.w * GATES + g]);
    }

    // ---- prologue t=0: gates0(0) = xproj(0) (h0(-1)=0) -> elem0
    gA[0 * GATES + g] = x0;
    gA[1 * GATES + g] = x1;
    gA[2 * GATES + g] = x2;
    gA[3 * GATES + g] = x3;
    __syncthreads();
    {
        const float* gr = gA + rr * GATES;
        float i_ = sig_f(gr[u]);
        float g_ = tanh_f(gr[128 + u]);
        float o_ = sig_f(gr[192 + u]);
        c0 = i_ * g_;
        h0s[rr * HID + u] = o_ * tanh_f(c0);
    }
    __syncthreads();
    x0 = p0; x1 = p1; x2 = p2; x3 = p3;

    const int gbase = g * HID;

    // ======== steady state: t = 1 .. SEQ-1 ========
#pragma unroll 1
    for (int t = 1; t < SEQ; ++t) {
        // prefetch xproj(t+1): covered by the full GEMM phase
        if (t + 1 < SEQ) {
            const int4 tk = tok4[t + 1];
            p0 = __ldg(&tab[(size_t)tk.x * GATES + g]);
            p1 = __ldg(&tab[(size_t)tk.y * GATES + g]);
            p2 = __ldg(&tab[(size_t)tk.z * GATES + g]);
            p3 = __ldg(&tab[(size_t)tk.w * GATES + g]);
        }

        // ---- fused GEMM phase (all weights from swizzled smem) -----
        // aB = gates1(t-1) = b1 + h0(t-1)·Wih1 + h1(t-2)·Whh1
        // aA = gates0(t)   = xproj(t) + h0(t-1)·Whh0
        {
            unsigned long long aB[4], aA[4];
#pragma unroll
            for (int r = 0; r < 4; ++r) aB[r] = pk2(b1, 0.f);
            aA[0] = pk2(x0, 0.f); aA[1] = pk2(x1, 0.f);
            aA[2] = pk2(x2, 0.f); aA[3] = pk2(x3, 0.f);
#pragma unroll 2
            for (int kc = 0; kc < 16; ++kc) {
                const int sw = gbase + (((kc + g) & 15) << 2);
                const ulonglong2 wiv = *(const ulonglong2*)&wi1s[sw];
                const ulonglong2 whv = *(const ulonglong2*)&wh1s[sw];
                const ulonglong2 w0v = *(const ulonglong2*)&w0s[sw];
#pragma unroll
                for (int r = 0; r < 4; ++r) {
                    const ulonglong2 h0v = *(const ulonglong2*)&h0s[r * HID + kc * 4];
                    const ulonglong2 h1v = *(const ulonglong2*)&h1s[r * HID + kc * 4];
                    fma2(aB[r], h0v.x, wiv.x);
                    fma2(aB[r], h0v.y, wiv.y);
                    fma2(aB[r], h1v.x, whv.x);
                    fma2(aB[r], h1v.y, whv.y);
                    fma2(aA[r], h0v.x, w0v.x);
                    fma2(aA[r], h0v.y, w0v.y);
                }
            }
#pragma unroll
            for (int r = 0; r < 4; ++r) {
                float lo, hi;
                upk2(aB[r], lo, hi);
                gB[r * GATES + g] = lo + hi;
                upk2(aA[r], lo, hi);
                gA[r * GATES + g] = lo + hi;
            }
        }
        __syncthreads();   // (1) gA/gB ready; all h reads complete

        // ---- fused elementwise: layer0(t) and layer1(t-1) for (rr,u)
        {
            const float* gr = gA + rr * GATES;
            float i_ = sig_f(gr[u]);
            float f_ = sig_f(gr[64 + u]);
            float g_ = tanh_f(gr[128 + u]);
            float o_ = sig_f(gr[192 + u]);
            c0 = f_ * c0 + i_ * g_;
            h0s[rr * HID + u] = o_ * tanh_f(c0);
        }
        {
            const float* gr = gB + rr * GATES;
            float i_ = sig_f(gr[u]);
            float f_ = sig_f(gr[64 + u]);
            float g_ = tanh_f(gr[128 + u]);
            float o_ = sig_f(gr[192 + u]);
            c1 = f_ * c1 + i_ * g_;
            h1s[rr * HID + u] = o_ * tanh_f(c1);
        }
        __syncthreads();   // (2) h0(t), h1(t-1) published

        x0 = p0; x1 = p1; x2 = p2; x3 = p3;
    }

    // ======== epilogue: gates1(SEQ-1) -> h1(SEQ-1) ========
    {
        unsigned long long a[4];
#pragma unroll
        for (int r = 0; r < 4; ++r) a[r] = pk2(b1, 0.f);
#pragma unroll 2
        for (int kc = 0; kc < 16; ++kc) {
            const int sw = gbase + (((kc + g) & 15) << 2);
            const ulonglong2 wiv = *(const ulonglong2*)&wi1s[sw];
            const ulonglong2 whv = *(const ulonglong2*)&wh1s[sw];
#pragma unroll
            for (int r = 0; r < 4; ++r) {
                const ulonglong2 h0v = *(const ulonglong2*)&h0s[r * HID + kc * 4];
                const ulonglong2 h1v = *(const ulonglong2*)&h1s[r * HID + kc * 4];
                fma2(a[r], h0v.x, wiv.x);
                fma2(a[r], h0v.y, wiv.y);
                fma2(a[r], h1v.x, whv.x);
                fma2(a[r], h1v.y, whv.y);
            }
        }
#pragma unroll
        for (int r = 0; r < 4; ++r) {
            float lo, hi; upk2(a[r], lo, hi);
            gB[r * GATES + g] = lo + hi;
        }
    }
    __syncthreads();
    {
        const float* gr = gB + rr * GATES;
        float i_ = sig_f(gr[u]);
        float f_ = sig_f(gr[64 + u]);
        float g_ = tanh_f(gr[128 + u]);
        float o_ = sig_f(gr[192 + u]);
        c1 = f_ * c1 + i_ * g_;
        h1s[rr * HID + u] = o_ * tanh_f(c1);
    }
    __syncthreads();

    // ---- Final FC + sigmoid on h1(SEQ-1)
    if (tid < 8) {
        int r = tid >> 1, o = tid & 1;
        float a = __ldg(&bfc[o]);
        for (int k = 0; k < HID; ++k)
            a = fmaf(h1s[r * HID + k], __ldg(&Wfc[o * HID + k]), a);
        out[(row0 + r) * 2 + o] = sig_f(a);
    }
}

// ======================================================================
extern "C" void kernel_launch(void* const* d_in, const int* in_sizes, int n_in,
                              void* d_out, int out_size) {
    const int*   seq32 = (const int*)d_in[0];
    const float* emb   = (const float*)d_in[1];
    const float* Wih0  = (const float*)d_in[2];
    const float* Whh0  = (const float*)d_in[3];
    const float* bih0  = (const float*)d_in[4];
    const float* bhh0  = (const float*)d_in[5];
    const float* Wih1  = (const float*)d_in[6];
    const float* Whh1  = (const float*)d_in[7];
    const float* bih1  = (const float*)d_in[8];
    const float* bhh1  = (const float*)d_in[9];
    const float* Wfc   = (const float*)d_in[10];
    const float* bfc   = (const float*)d_in[11];
    float* out = (float*)d_out;

    float* tab = nullptr;
    cudaGetSymbolAddress((void**)&tab, g_tab);

    // smem: 3 weight matrices (3*16384) + h0(256) + h1(256) + gA(1024) +
    //       gB(1024) + tok4(512*4 ints)  = 210 KB
    const int smem2 = (3 * 16384 + 256 + 256 + 1024 + 1024 + SEQ * 4) * 4;
    cudaFuncSetAttribute(k_scan, cudaFuncAttributeMaxDynamicSharedMemorySize, smem2);

    dim3 gtab((VOCAB + 127) / 128, 2);
    k_table<<<gtab, 256>>>(emb, Wih0, bih0, bhh0, tab);
    k_scan<<<BATCH / 4, 256, smem2>>>(seq32, tab, Whh0, Wih1, Whh1,
                                      bih1, bhh1, Wfc, bfc, out);
}